// round 15
// baseline (speedup 1.0000x reference)
#include <cuda_runtime.h>
#include <cuda_bf16.h>
#include <cstdint>
#include <math.h>

#define C_CLS 100
#define KP    8
#define D_DIM 512
#define LAMBDA 0.1f
#define WS 0.0625f
#define WO (0.5f/99.0f)
#define SQWS 0.25f
#define SQWO 0.07106690545187014f
#define SQWSWO 0.017766726362967535f
#define INV_SUB_T 20.0f
#define INV_PRIOR_T (1.0f/0.07f)
#define INV_ROUT_T (1.0f/0.07f)
#define NEPS 1e-8f
#define MSZ 107

#define MTILE 128
#define NTILE 72
#define CPT 8
#define NT_TILES 13
#define STAGE_BYTES 25600   // A 16384 + B 9216
#define NSTAGE 3
#define SMEM_DYN (NSTAGE * STAGE_BYTES)

typedef unsigned long long u64;
typedef unsigned int u32;

__device__ __align__(16) float g_Bmat[900 * D_DIM];
__device__ __align__(16) float g_centers[C_CLS * D_DIM];
__device__ __align__(16) float g_bvec[C_CLS * D_DIM];
__device__ __align__(16) float g_rinv[32768];
__device__ float g_GCC[C_CLS * C_CLS];
__device__ float g_GPC[C_CLS * KP * C_CLS];
__device__ float g_GPP[C_CLS * KP * KP];
__device__ float g_CB[C_CLS * C_CLS];
__device__ float g_PB[C_CLS * KP];
// packed bf16 hi|lo: A [32768][1024], B [1080][1024] (rows >= 900 zero)
__device__ __align__(16) __nv_bfloat16 g_Apack[(size_t)32768 * 1024];
__device__ __align__(16) __nv_bfloat16 g_Bpack[(size_t)1080 * 1024];

__device__ __forceinline__ float warp_sum(float s) {
#pragma unroll
    for (int o = 16; o > 0; o >>= 1) s += __shfl_xor_sync(0xffffffffu, s, o);
    return s;
}

__device__ __forceinline__ float warp_dot512(const float* __restrict__ u,
                                             const float* __restrict__ v, int lane) {
    float s = 0.f;
#pragma unroll
    for (int i = 0; i < 4; i++) {
        float4 a = *reinterpret_cast<const float4*>(u + lane * 4 + i * 128);
        float4 b = *reinterpret_cast<const float4*>(v + lane * 4 + i * 128);
        s += a.x * b.x + a.y * b.y + a.z * b.z + a.w * b.w;
    }
    return warp_sum(s);
}

__device__ __forceinline__ u32 smem_u32(const void* p) {
    u32 a;
    asm("{ .reg .u64 t; cvta.to.shared.u64 t, %1; cvt.u32.u64 %0, t; }" : "=r"(a) : "l"(p));
    return a;
}

__device__ __forceinline__ u64 pack4bf(__nv_bfloat16 a, __nv_bfloat16 b,
                                       __nv_bfloat16 c, __nv_bfloat16 d) {
    return (u64)__bfloat16_as_ushort(a) | ((u64)__bfloat16_as_ushort(b) << 16) |
           ((u64)__bfloat16_as_ushort(c) << 32) | ((u64)__bfloat16_as_ushort(d) << 48);
}

__device__ __forceinline__ void split_hl(float x, __nv_bfloat16& hi, __nv_bfloat16& lo) {
    hi = __float2bfloat16(x);
    lo = __float2bfloat16(x - __bfloat162float(hi));
}

// -------- launch 1: pnorm (blocks 0..99) + rnorm + A hi/lo pack --------
__global__ void k_prep(const float* __restrict__ h, const float* __restrict__ P) {
    int lane = threadIdx.x & 31;
    if (blockIdx.x < 100) {
        int c = blockIdx.x, w = threadIdx.x >> 5;
        const float* src = P + ((size_t)c * KP + w) * D_DIM + lane * 4;
        float4 a[4]; float s = 0.f;
#pragma unroll
        for (int i = 0; i < 4; i++) {
            a[i] = *reinterpret_cast<const float4*>(src + i * 128);
            s += a[i].x*a[i].x + a[i].y*a[i].y + a[i].z*a[i].z + a[i].w*a[i].w;
        }
        s = warp_sum(s);
        float inv = 1.0f / fmaxf(sqrtf(s), NEPS);
        float* dst = g_Bmat + ((size_t)c * 9 + w) * D_DIM + lane * 4;
#pragma unroll
        for (int i = 0; i < 4; i++) {
            float4 o; o.x=a[i].x*inv; o.y=a[i].y*inv; o.z=a[i].z*inv; o.w=a[i].w*inv;
            *reinterpret_cast<float4*>(dst + i * 128) = o;
        }
    } else {
        int row = (blockIdx.x - 100) * 8 + (threadIdx.x >> 5);
        const float* r = h + (size_t)row * D_DIM + lane * 4;
        float4 a[4]; float s = 0.f;
#pragma unroll
        for (int i = 0; i < 4; i++) {
            a[i] = *reinterpret_cast<const float4*>(r + i * 128);
            s += a[i].x*a[i].x + a[i].y*a[i].y + a[i].z*a[i].z + a[i].w*a[i].w;
        }
        s = warp_sum(s);
        if (lane == 0) g_rinv[row] = 1.0f / fmaxf(sqrtf(s), NEPS);
#pragma unroll
        for (int i = 0; i < 4; i++) {
            int col = lane * 4 + i * 128;
            __nv_bfloat16 h0,h1,h2,h3,l0,l1,l2,l3;
            split_hl(a[i].x,h0,l0); split_hl(a[i].y,h1,l1);
            split_hl(a[i].z,h2,l2); split_hl(a[i].w,h3,l3);
            *(u64*)(g_Apack + (size_t)row * 1024 + col)       = pack4bf(h0,h1,h2,h3);
            *(u64*)(g_Apack + (size_t)row * 1024 + 512 + col) = pack4bf(l0,l1,l2,l3);
        }
    }
}

// -------- launch 2: centers --------
__global__ void k_centers() {
    int c = blockIdx.x, tid = threadIdx.x;
    __shared__ float red[256];
    __shared__ float sm[D_DIM];
    float acc = 0.f;
    for (int d = tid; d < D_DIM; d += 256) {
        float m = 0.f;
#pragma unroll
        for (int k = 0; k < KP; k++) m += g_Bmat[((size_t)c * 9 + k) * D_DIM + d];
        m *= 0.125f;
        sm[d] = m; acc += m * m;
    }
    red[tid] = acc; __syncthreads();
    for (int s = 128; s > 0; s >>= 1) { if (tid < s) red[tid] += red[tid + s]; __syncthreads(); }
    float inv = 1.0f / fmaxf(sqrtf(red[0]), NEPS);
    for (int d = tid; d < D_DIM; d += 256) g_centers[(size_t)c * D_DIM + d] = sm[d] * inv;
}

// -------- launch 3: RHS --------
__global__ void k_bvec() {
    int c = blockIdx.x, tid = threadIdx.x;
    for (int d = tid; d < D_DIM; d += 256) {
        float cs = 0.f;
        for (int j = 0; j < C_CLS; j++) cs += g_centers[(size_t)j * D_DIM + d];
        float sp = 0.f;
#pragma unroll
        for (int k = 0; k < KP; k++) sp += g_Bmat[((size_t)c * 9 + k) * D_DIM + d];
        g_bvec[(size_t)c * D_DIM + d] =
            WS * sp - WO * (cs - g_centers[(size_t)c * D_DIM + d]);
    }
}

// -------- launch 4: Grams --------
__global__ void k_grams() {
    int blk = blockIdx.x;
    int w = threadIdx.x >> 5, lane = threadIdx.x & 31;
    if (blk < 100) {
        const float* ca = g_centers + (size_t)blk * D_DIM;
        for (int b = w; b < C_CLS; b += 8) {
            float s = warp_dot512(ca, g_centers + (size_t)b * D_DIM, lane);
            if (lane == 0) g_GCC[blk * C_CLS + b] = s;
        }
    } else if (blk < 900) {
        int pr = blk - 100;
        const float* prow = g_Bmat + ((size_t)(pr >> 3) * 9 + (pr & 7)) * D_DIM;
        for (int j = w; j < C_CLS; j += 8) {
            float s = warp_dot512(prow, g_centers + (size_t)j * D_DIM, lane);
            if (lane == 0) g_GPC[pr * C_CLS + j] = s;
        }
    } else if (blk < 1000) {
        int c = blk - 900;
        for (int e = w; e < 64; e += 8) {
            float s = warp_dot512(g_Bmat + ((size_t)c * 9 + (e >> 3)) * D_DIM,
                                  g_Bmat + ((size_t)c * 9 + (e & 7)) * D_DIM, lane);
            if (lane == 0) g_GPP[c * 64 + e] = s;
        }
    } else {
        int c = blk - 1000;
        const float* bv = g_bvec + (size_t)c * D_DIM;
        for (int idx = w; idx < 108; idx += 8) {
            float s;
            if (idx < C_CLS) {
                s = warp_dot512(g_centers + (size_t)idx * D_DIM, bv, lane);
                if (lane == 0) g_CB[c * C_CLS + idx] = s;
            } else {
                s = warp_dot512(g_Bmat + ((size_t)c * 9 + (idx - 100)) * D_DIM, bv, lane);
                if (lane == 0) g_PB[c * KP + (idx - 100)] = s;
            }
        }
    }
}

// -------- launch 5: Woodbury solve + B hi/lo pack --------
__global__ __launch_bounds__(256) void k_solve() {
    int c = blockIdx.x, tid = threadIdx.x;
    __shared__ float M[MSZ * MSZ];
    __shared__ float v[MSZ];
    for (int idx = tid; idx < MSZ * MSZ; idx += 256) {
        int i = idx / MSZ, j = idx % MSZ;
        if (j > i) continue;
        float val;
        if (i < 8) {
            val = WS * g_GPP[c * 64 + i * 8 + j];
        } else {
            int ci = (i - 8) + ((i - 8) >= c ? 1 : 0);
            if (j < 8) val = SQWSWO * g_GPC[(c * 8 + j) * C_CLS + ci];
            else {
                int cj = (j - 8) + ((j - 8) >= c ? 1 : 0);
                val = WO * g_GCC[ci * C_CLS + cj];
            }
        }
        if (i == j) val += LAMBDA;
        M[i * MSZ + j] = val;
    }
    if (tid < MSZ) {
        if (tid < 8) v[tid] = SQWS * g_PB[c * KP + tid];
        else {
            int ci = (tid - 8) + ((tid - 8) >= c ? 1 : 0);
            v[tid] = SQWO * g_CB[c * C_CLS + ci];
        }
    }
    __syncthreads();
    for (int k = 0; k < MSZ; k++) {
        if (tid == 0) M[k * MSZ + k] = sqrtf(M[k * MSZ + k]);
        __syncthreads();
        float dk = M[k * MSZ + k];
        for (int i = k + 1 + tid; i < MSZ; i += 256) M[i * MSZ + k] /= dk;
        __syncthreads();
        for (int j = k + 1; j < MSZ; j++) {
            float ljk = M[j * MSZ + k];
            for (int i = j + tid; i < MSZ; i += 256) M[i * MSZ + j] -= M[i * MSZ + k] * ljk;
        }
        __syncthreads();
    }
    for (int k = 0; k < MSZ; k++) {
        if (tid == 0) v[k] /= M[k * MSZ + k];
        __syncthreads();
        float vk = v[k];
        for (int i = k + 1 + tid; i < MSZ; i += 256) v[i] -= M[i * MSZ + k] * vk;
        __syncthreads();
    }
    for (int k = MSZ - 1; k >= 0; k--) {
        if (tid == 0) v[k] /= M[k * MSZ + k];
        __syncthreads();
        float vk = v[k];
        for (int i = tid; i < k; i += 256) v[i] -= M[k * MSZ + i] * vk;
        __syncthreads();
    }
    for (int d = tid; d < D_DIM; d += 256) {
        float acc = g_bvec[(size_t)c * D_DIM + d];
#pragma unroll
        for (int i = 0; i < 8; i++)
            acc -= SQWS * g_Bmat[((size_t)c * 9 + i) * D_DIM + d] * v[i];
        for (int j = 0; j < C_CLS; j++) {
            if (j == c) continue;
            int i = 8 + j - (j > c ? 1 : 0);
            acc -= SQWO * g_centers[(size_t)j * D_DIM + d] * v[i];
        }
        float wv = acc * (1.0f / LAMBDA) * INV_ROUT_T;
        __nv_bfloat16 hi, lo; split_hl(wv, hi, lo);
        g_Bpack[((size_t)c * 9 + 8) * 1024 + d] = hi;
        g_Bpack[((size_t)c * 9 + 8) * 1024 + 512 + d] = lo;
    }
    for (int idx = tid; idx < 8 * D_DIM; idx += 256) {
        int j = idx >> 9, d = idx & 511;
        float x = g_Bmat[((size_t)c * 9 + j) * D_DIM + d];
        __nv_bfloat16 hi, lo; split_hl(x, hi, lo);
        g_Bpack[((size_t)c * 9 + j) * 1024 + d] = hi;
        g_Bpack[((size_t)c * 9 + j) * 1024 + 512 + d] = lo;
    }
}

// -------- launch 6: bf16 mma.sync GEMM, 3-stage pipeline + fused epilogue --------
__device__ __forceinline__ void cp16(u32 dst, const void* src) {
    asm volatile("cp.async.cg.shared.global [%0], [%1], 16;" :: "r"(dst), "l"(src));
}

// seg pairs: (Aseg, Bseg) per 8-chunk group: (hi,hi), (hi,lo), (lo,hi)
__device__ __forceinline__ void load_chunk(char* buf, int row0, int nt, int t, int tid) {
    int grp = t >> 3, kc = t & 7;
    int sa = (grp == 2) ? 1 : 0;
    int sb = (grp == 1) ? 1 : 0;
    u32 bufA = smem_u32(buf);
    u32 bufB = bufA + 16384;
    for (int u = tid; u < 1024; u += 384) {
        int r = u >> 3, g = u & 7;
        cp16(bufA + r * 128 + ((g ^ (r & 7)) * 16),
             g_Apack + (size_t)(row0 + r) * 1024 + sa * 512 + kc * 64 + g * 8);
    }
    for (int u = tid; u < 576; u += 384) {
        int n = u >> 3, g = u & 7;
        cp16(bufB + n * 128 + ((g ^ (n & 7)) * 16),
             g_Bpack + (size_t)(nt * NTILE + n) * 1024 + sb * 512 + kc * 64 + g * 8);
    }
    asm volatile("cp.async.commit_group;" ::: "memory");
}

__global__ __launch_bounds__(384) void k_mm(float* __restrict__ out) {
    extern __shared__ __align__(16) char dsm[];
    int tid = threadIdx.x, wid = tid >> 5, lane = tid & 31;
    int wm = wid & 3, wn = wid >> 2;            // 4 x 3 warp grid
    int row0 = blockIdx.x * MTILE;
    int nt = blockIdx.y;

    float acc[2][3][4];
#pragma unroll
    for (int mi = 0; mi < 2; mi++)
#pragma unroll
        for (int ni = 0; ni < 3; ni++)
#pragma unroll
            for (int c = 0; c < 4; c++) acc[mi][ni][c] = 0.f;

    // prologue: 2 chunks in flight
    load_chunk(dsm + 0 * STAGE_BYTES, row0, nt, 0, tid);
    load_chunk(dsm + 1 * STAGE_BYTES, row0, nt, 1, tid);

    int buf_idx = 0;
    for (int t = 0; t < 24; t++) {
        // wait for chunk t (leave the younger one in flight)
        if (t < 23) asm volatile("cp.async.wait_group 1;" ::: "memory");
        else        asm volatile("cp.async.wait_group 0;" ::: "memory");
        __syncthreads();   // chunk t visible to all; buffer (t-1) drained by all

        // issue chunk t+2 into the buffer vacated by chunk t-1
        if (t + 2 < 24)
            load_chunk(dsm + ((buf_idx + 2) % NSTAGE) * STAGE_BYTES, row0, nt, t + 2, tid);

        char* buf = dsm + buf_idx * STAGE_BYTES;
        u32 bufA = smem_u32(buf);
        u32 bufB = bufA + 16384;

        // preload B frags: 3 ni x 2 kstep-pairs via ldmatrix.x4
        u32 bfr[3][4][2];
#pragma unroll
        for (int ni = 0; ni < 3; ni++) {
#pragma unroll
            for (int kp = 0; kp < 2; kp++) {
                int n = wn * 24 + ni * 8 + (lane & 7);
                int g = kp * 4 + (lane >> 3);
                u32 addr = bufB + n * 128 + ((g ^ (n & 7)) * 16);
                u32 r0, r1, r2, r3;
                asm volatile("ldmatrix.sync.aligned.m8n8.x4.shared.b16 {%0,%1,%2,%3}, [%4];"
                             : "=r"(r0), "=r"(r1), "=r"(r2), "=r"(r3) : "r"(addr));
                bfr[ni][kp * 2 + 0][0] = r0; bfr[ni][kp * 2 + 0][1] = r1;
                bfr[ni][kp * 2 + 1][0] = r2; bfr[ni][kp * 2 + 1][1] = r3;
            }
        }
#pragma unroll
        for (int ks = 0; ks < 4; ks++) {
            u32 afr[2][4];
#pragma unroll
            for (int mi = 0; mi < 2; mi++) {
                int r = wm * 32 + mi * 16 + (lane & 15);
                int g = ks * 2 + (lane >> 4);
                u32 addr = bufA + r * 128 + ((g ^ (r & 7)) * 16);
                asm volatile("ldmatrix.sync.aligned.m8n8.x4.shared.b16 {%0,%1,%2,%3}, [%4];"
                             : "=r"(afr[mi][0]), "=r"(afr[mi][1]),
                               "=r"(afr[mi][2]), "=r"(afr[mi][3]) : "r"(addr));
            }
#pragma unroll
            for (int mi = 0; mi < 2; mi++)
#pragma unroll
                for (int ni = 0; ni < 3; ni++)
                    asm volatile(
                        "mma.sync.aligned.m16n8k16.row.col.f32.bf16.bf16.f32 "
                        "{%0,%1,%2,%3}, {%4,%5,%6,%7}, {%8,%9}, {%0,%1,%2,%3};"
                        : "+f"(acc[mi][ni][0]), "+f"(acc[mi][ni][1]),
                          "+f"(acc[mi][ni][2]), "+f"(acc[mi][ni][3])
                        : "r"(afr[mi][0]), "r"(afr[mi][1]), "r"(afr[mi][2]), "r"(afr[mi][3]),
                          "r"(bfr[ni][ks][0]), "r"(bfr[ni][ks][1]));
        }
        buf_idx = (buf_idx + 1) % NSTAGE;
    }
    __syncthreads();   // all compute done before dsm reuse as sAcc

    // stage accumulators to smem for class-aligned epilogue
    float* sAcc = reinterpret_cast<float*>(dsm);
#pragma unroll
    for (int mi = 0; mi < 2; mi++)
#pragma unroll
        for (int ni = 0; ni < 3; ni++)
#pragma unroll
            for (int c = 0; c < 4; c++) {
                int rl = wm * 32 + mi * 16 + (lane >> 2) + ((c >> 1) & 1) * 8;
                int cl = wn * 24 + ni * 8 + (lane & 3) * 2 + (c & 1);
                sAcc[rl * NTILE + cl] = acc[mi][ni][c];
            }
    __syncthreads();

    for (int idx = tid; idx < MTILE * CPT; idx += 384) {
        int rl = idx >> 3, cl = idx & 7;
        int cls = nt * CPT + cl;
        if (cls >= C_CLS) continue;
        int row = row0 + rl;
        float ri = g_rinv[row];
        const float* a = sAcc + rl * NTILE + cl * 9;
        float cs[8], mx = -1e30f;
#pragma unroll
        for (int j = 0; j < 8; j++) { cs[j] = a[j] * ri; mx = fmaxf(mx, cs[j]); }
        float den = 0.f, num = 0.f;
#pragma unroll
        for (int j = 0; j < 8; j++) {
            float e = __expf((cs[j] - mx) * INV_SUB_T);
            den += e; num += e * cs[j];
        }
        out[(size_t)row * C_CLS + cls] = (num / den) * INV_PRIOR_T + a[8] * ri;
    }
}

extern "C" void kernel_launch(void* const* d_in, const int* in_sizes, int n_in,
                              void* d_out, int out_size) {
    const float* h = (const float*)d_in[0];
    const float* P = (const float*)d_in[1];
    float* out = (float*)d_out;
    (void)in_sizes; (void)n_in; (void)out_size;

    cudaFuncSetAttribute(k_mm, cudaFuncAttributeMaxDynamicSharedMemorySize, SMEM_DYN);

    k_prep<<<4196, 256>>>(h, P);
    k_centers<<<100, 256>>>();
    k_bvec<<<100, 256>>>();
    k_grams<<<1100, 256>>>();
    k_solve<<<100, 256>>>();
    k_mm<<<dim3(256, NT_TILES), 384, SMEM_DYN>>>(out);
}

// round 17
// speedup vs baseline: 1.6116x; 1.6116x over previous
#include <cuda_runtime.h>
#include <cuda_bf16.h>
#include <cstdint>
#include <math.h>

#define C_CLS 100
#define KP    8
#define D_DIM 512
#define LAMBDA 0.1f
#define WS 0.0625f
#define WO (0.5f/99.0f)
#define SQWS 0.25f
#define SQWO 0.07106690545187014f
#define SQWSWO 0.017766726362967535f
#define INV_SUB_T 20.0f
#define INV_PRIOR_T (1.0f/0.07f)
#define INV_ROUT_T (1.0f/0.07f)
#define NEPS 1e-8f
#define MSZ 107

#define MTILE 128
#define NTILE 72
#define CPT 8
#define NT_TILES 13
// stage: A 16384 + B_hi 9216 + B_lo 9216
#define STAGE_BYTES 34816
#define SMEM_DYN (2 * STAGE_BYTES)

typedef unsigned long long u64;
typedef unsigned int u32;

__device__ __align__(16) float g_Bmat[900 * D_DIM];
__device__ __align__(16) float g_centers[C_CLS * D_DIM];
__device__ __align__(16) float g_bvec[C_CLS * D_DIM];
__device__ __align__(16) float g_rinv[32768];
__device__ float g_GCC[C_CLS * C_CLS];
__device__ float g_GPC[C_CLS * KP * C_CLS];
__device__ float g_GPP[C_CLS * KP * KP];
__device__ float g_CB[C_CLS * C_CLS];
__device__ float g_PB[C_CLS * KP];
// packed bf16 hi|lo: A [32768][1024], B [1080][1024] (rows >= 900 zero)
__device__ __align__(16) __nv_bfloat16 g_Apack[(size_t)32768 * 1024];
__device__ __align__(16) __nv_bfloat16 g_Bpack[(size_t)1080 * 1024];

__device__ __forceinline__ float warp_sum(float s) {
#pragma unroll
    for (int o = 16; o > 0; o >>= 1) s += __shfl_xor_sync(0xffffffffu, s, o);
    return s;
}

__device__ __forceinline__ float warp_dot512(const float* __restrict__ u,
                                             const float* __restrict__ v, int lane) {
    float s = 0.f;
#pragma unroll
    for (int i = 0; i < 4; i++) {
        float4 a = *reinterpret_cast<const float4*>(u + lane * 4 + i * 128);
        float4 b = *reinterpret_cast<const float4*>(v + lane * 4 + i * 128);
        s += a.x * b.x + a.y * b.y + a.z * b.z + a.w * b.w;
    }
    return warp_sum(s);
}

__device__ __forceinline__ u32 smem_u32(const void* p) {
    u32 a;
    asm("{ .reg .u64 t; cvta.to.shared.u64 t, %1; cvt.u32.u64 %0, t; }" : "=r"(a) : "l"(p));
    return a;
}

__device__ __forceinline__ u64 pack4bf(__nv_bfloat16 a, __nv_bfloat16 b,
                                       __nv_bfloat16 c, __nv_bfloat16 d) {
    return (u64)__bfloat16_as_ushort(a) | ((u64)__bfloat16_as_ushort(b) << 16) |
           ((u64)__bfloat16_as_ushort(c) << 32) | ((u64)__bfloat16_as_ushort(d) << 48);
}

__device__ __forceinline__ void split_hl(float x, __nv_bfloat16& hi, __nv_bfloat16& lo) {
    hi = __float2bfloat16(x);
    lo = __float2bfloat16(x - __bfloat162float(hi));
}

// -------- launch 1: pnorm (blocks 0..99) + rnorm + A hi/lo pack --------
__global__ void k_prep(const float* __restrict__ h, const float* __restrict__ P) {
    int lane = threadIdx.x & 31;
    if (blockIdx.x < 100) {
        int c = blockIdx.x, w = threadIdx.x >> 5;
        const float* src = P + ((size_t)c * KP + w) * D_DIM + lane * 4;
        float4 a[4]; float s = 0.f;
#pragma unroll
        for (int i = 0; i < 4; i++) {
            a[i] = *reinterpret_cast<const float4*>(src + i * 128);
            s += a[i].x*a[i].x + a[i].y*a[i].y + a[i].z*a[i].z + a[i].w*a[i].w;
        }
        s = warp_sum(s);
        float inv = 1.0f / fmaxf(sqrtf(s), NEPS);
        float* dst = g_Bmat + ((size_t)c * 9 + w) * D_DIM + lane * 4;
#pragma unroll
        for (int i = 0; i < 4; i++) {
            float4 o; o.x=a[i].x*inv; o.y=a[i].y*inv; o.z=a[i].z*inv; o.w=a[i].w*inv;
            *reinterpret_cast<float4*>(dst + i * 128) = o;
        }
    } else {
        int row = (blockIdx.x - 100) * 8 + (threadIdx.x >> 5);
        const float* r = h + (size_t)row * D_DIM + lane * 4;
        float4 a[4]; float s = 0.f;
#pragma unroll
        for (int i = 0; i < 4; i++) {
            a[i] = *reinterpret_cast<const float4*>(r + i * 128);
            s += a[i].x*a[i].x + a[i].y*a[i].y + a[i].z*a[i].z + a[i].w*a[i].w;
        }
        s = warp_sum(s);
        if (lane == 0) g_rinv[row] = 1.0f / fmaxf(sqrtf(s), NEPS);
#pragma unroll
        for (int i = 0; i < 4; i++) {
            int col = lane * 4 + i * 128;
            __nv_bfloat16 h0,h1,h2,h3,l0,l1,l2,l3;
            split_hl(a[i].x,h0,l0); split_hl(a[i].y,h1,l1);
            split_hl(a[i].z,h2,l2); split_hl(a[i].w,h3,l3);
            *(u64*)(g_Apack + (size_t)row * 1024 + col)       = pack4bf(h0,h1,h2,h3);
            *(u64*)(g_Apack + (size_t)row * 1024 + 512 + col) = pack4bf(l0,l1,l2,l3);
        }
    }
}

// -------- launch 2: centers --------
__global__ void k_centers() {
    int c = blockIdx.x, tid = threadIdx.x;
    __shared__ float red[256];
    __shared__ float sm[D_DIM];
    float acc = 0.f;
    for (int d = tid; d < D_DIM; d += 256) {
        float m = 0.f;
#pragma unroll
        for (int k = 0; k < KP; k++) m += g_Bmat[((size_t)c * 9 + k) * D_DIM + d];
        m *= 0.125f;
        sm[d] = m; acc += m * m;
    }
    red[tid] = acc; __syncthreads();
    for (int s = 128; s > 0; s >>= 1) { if (tid < s) red[tid] += red[tid + s]; __syncthreads(); }
    float inv = 1.0f / fmaxf(sqrtf(red[0]), NEPS);
    for (int d = tid; d < D_DIM; d += 256) g_centers[(size_t)c * D_DIM + d] = sm[d] * inv;
}

// -------- launch 3: RHS --------
__global__ void k_bvec() {
    int c = blockIdx.x, tid = threadIdx.x;
    for (int d = tid; d < D_DIM; d += 256) {
        float cs = 0.f;
        for (int j = 0; j < C_CLS; j++) cs += g_centers[(size_t)j * D_DIM + d];
        float sp = 0.f;
#pragma unroll
        for (int k = 0; k < KP; k++) sp += g_Bmat[((size_t)c * 9 + k) * D_DIM + d];
        g_bvec[(size_t)c * D_DIM + d] =
            WS * sp - WO * (cs - g_centers[(size_t)c * D_DIM + d]);
    }
}

// -------- launch 4: Grams --------
__global__ void k_grams() {
    int blk = blockIdx.x;
    int w = threadIdx.x >> 5, lane = threadIdx.x & 31;
    if (blk < 100) {
        const float* ca = g_centers + (size_t)blk * D_DIM;
        for (int b = w; b < C_CLS; b += 8) {
            float s = warp_dot512(ca, g_centers + (size_t)b * D_DIM, lane);
            if (lane == 0) g_GCC[blk * C_CLS + b] = s;
        }
    } else if (blk < 900) {
        int pr = blk - 100;
        const float* prow = g_Bmat + ((size_t)(pr >> 3) * 9 + (pr & 7)) * D_DIM;
        for (int j = w; j < C_CLS; j += 8) {
            float s = warp_dot512(prow, g_centers + (size_t)j * D_DIM, lane);
            if (lane == 0) g_GPC[pr * C_CLS + j] = s;
        }
    } else if (blk < 1000) {
        int c = blk - 900;
        for (int e = w; e < 64; e += 8) {
            float s = warp_dot512(g_Bmat + ((size_t)c * 9 + (e >> 3)) * D_DIM,
                                  g_Bmat + ((size_t)c * 9 + (e & 7)) * D_DIM, lane);
            if (lane == 0) g_GPP[c * 64 + e] = s;
        }
    } else {
        int c = blk - 1000;
        const float* bv = g_bvec + (size_t)c * D_DIM;
        for (int idx = w; idx < 108; idx += 8) {
            float s;
            if (idx < C_CLS) {
                s = warp_dot512(g_centers + (size_t)idx * D_DIM, bv, lane);
                if (lane == 0) g_CB[c * C_CLS + idx] = s;
            } else {
                s = warp_dot512(g_Bmat + ((size_t)c * 9 + (idx - 100)) * D_DIM, bv, lane);
                if (lane == 0) g_PB[c * KP + (idx - 100)] = s;
            }
        }
    }
}

// -------- launch 5: Woodbury solve + B hi/lo pack --------
__global__ __launch_bounds__(256) void k_solve() {
    int c = blockIdx.x, tid = threadIdx.x;
    __shared__ float M[MSZ * MSZ];
    __shared__ float v[MSZ];
    for (int idx = tid; idx < MSZ * MSZ; idx += 256) {
        int i = idx / MSZ, j = idx % MSZ;
        if (j > i) continue;
        float val;
        if (i < 8) {
            val = WS * g_GPP[c * 64 + i * 8 + j];
        } else {
            int ci = (i - 8) + ((i - 8) >= c ? 1 : 0);
            if (j < 8) val = SQWSWO * g_GPC[(c * 8 + j) * C_CLS + ci];
            else {
                int cj = (j - 8) + ((j - 8) >= c ? 1 : 0);
                val = WO * g_GCC[ci * C_CLS + cj];
            }
        }
        if (i == j) val += LAMBDA;
        M[i * MSZ + j] = val;
    }
    if (tid < MSZ) {
        if (tid < 8) v[tid] = SQWS * g_PB[c * KP + tid];
        else {
            int ci = (tid - 8) + ((tid - 8) >= c ? 1 : 0);
            v[tid] = SQWO * g_CB[c * C_CLS + ci];
        }
    }
    __syncthreads();
    for (int k = 0; k < MSZ; k++) {
        if (tid == 0) M[k * MSZ + k] = sqrtf(M[k * MSZ + k]);
        __syncthreads();
        float dk = M[k * MSZ + k];
        for (int i = k + 1 + tid; i < MSZ; i += 256) M[i * MSZ + k] /= dk;
        __syncthreads();
        for (int j = k + 1; j < MSZ; j++) {
            float ljk = M[j * MSZ + k];
            for (int i = j + tid; i < MSZ; i += 256) M[i * MSZ + j] -= M[i * MSZ + k] * ljk;
        }
        __syncthreads();
    }
    for (int k = 0; k < MSZ; k++) {
        if (tid == 0) v[k] /= M[k * MSZ + k];
        __syncthreads();
        float vk = v[k];
        for (int i = k + 1 + tid; i < MSZ; i += 256) v[i] -= M[i * MSZ + k] * vk;
        __syncthreads();
    }
    for (int k = MSZ - 1; k >= 0; k--) {
        if (tid == 0) v[k] /= M[k * MSZ + k];
        __syncthreads();
        float vk = v[k];
        for (int i = tid; i < k; i += 256) v[i] -= M[k * MSZ + i] * vk;
        __syncthreads();
    }
    for (int d = tid; d < D_DIM; d += 256) {
        float acc = g_bvec[(size_t)c * D_DIM + d];
#pragma unroll
        for (int i = 0; i < 8; i++)
            acc -= SQWS * g_Bmat[((size_t)c * 9 + i) * D_DIM + d] * v[i];
        for (int j = 0; j < C_CLS; j++) {
            if (j == c) continue;
            int i = 8 + j - (j > c ? 1 : 0);
            acc -= SQWO * g_centers[(size_t)j * D_DIM + d] * v[i];
        }
        float wv = acc * (1.0f / LAMBDA) * INV_ROUT_T;
        __nv_bfloat16 hi, lo; split_hl(wv, hi, lo);
        g_Bpack[((size_t)c * 9 + 8) * 1024 + d] = hi;
        g_Bpack[((size_t)c * 9 + 8) * 1024 + 512 + d] = lo;
    }
    for (int idx = tid; idx < 8 * D_DIM; idx += 256) {
        int j = idx >> 9, d = idx & 511;
        float x = g_Bmat[((size_t)c * 9 + j) * D_DIM + d];
        __nv_bfloat16 hi, lo; split_hl(x, hi, lo);
        g_Bpack[((size_t)c * 9 + j) * 1024 + d] = hi;
        g_Bpack[((size_t)c * 9 + j) * 1024 + 512 + d] = lo;
    }
}

// -------- launch 6: bf16 mma.sync GEMM (A-hi reuse schedule) + fused epilogue --------
__device__ __forceinline__ void cp16(u32 dst, const void* src) {
    asm volatile("cp.async.cg.shared.global [%0], [%1], 16;" :: "r"(dst), "l"(src));
}

// super-chunks: sc 0..7  -> A-hi[kc] + B-hi[kc] + B-lo[kc]  (2 mma passes)
//               sc 8..15 -> A-lo[kc] + B-hi[kc]             (1 mma pass)
__device__ __forceinline__ void load_chunk(char* buf, int row0, int nt, int sc, int tid) {
    int kc = sc & 7;
    int sa = (sc >= 8) ? 1 : 0;
    u32 bufA = smem_u32(buf);
    u32 bufB = bufA + 16384;
    for (int u = tid; u < 1024; u += 384) {
        int r = u >> 3, g = u & 7;
        cp16(bufA + r * 128 + ((g ^ (r & 7)) * 16),
             g_Apack + (size_t)(row0 + r) * 1024 + sa * 512 + kc * 64 + g * 8);
    }
    // B-hi always
    for (int u = tid; u < 576; u += 384) {
        int n = u >> 3, g = u & 7;
        cp16(bufB + n * 128 + ((g ^ (n & 7)) * 16),
             g_Bpack + (size_t)(nt * NTILE + n) * 1024 + kc * 64 + g * 8);
    }
    // B-lo only for A-hi super-chunks
    if (sc < 8) {
        u32 bufB2 = bufB + 9216;
        for (int u = tid; u < 576; u += 384) {
            int n = u >> 3, g = u & 7;
            cp16(bufB2 + n * 128 + ((g ^ (n & 7)) * 16),
                 g_Bpack + (size_t)(nt * NTILE + n) * 1024 + 512 + kc * 64 + g * 8);
        }
    }
    asm volatile("cp.async.commit_group;" ::: "memory");
}

__global__ __launch_bounds__(384) void k_mm(float* __restrict__ out) {
    extern __shared__ __align__(16) char dsm[];
    int tid = threadIdx.x, wid = tid >> 5, lane = tid & 31;
    int wm = wid & 3, wn = wid >> 2;            // 4 x 3 warp grid
    int row0 = blockIdx.x * MTILE;
    int nt = blockIdx.y;

    float acc[2][3][4];
#pragma unroll
    for (int mi = 0; mi < 2; mi++)
#pragma unroll
        for (int ni = 0; ni < 3; ni++)
#pragma unroll
            for (int c = 0; c < 4; c++) acc[mi][ni][c] = 0.f;

    load_chunk(dsm, row0, nt, 0, tid);

    for (int sc = 0; sc < 16; sc++) {
        if (sc + 1 < 16) {
            load_chunk(dsm + ((sc + 1) & 1) * STAGE_BYTES, row0, nt, sc + 1, tid);
            asm volatile("cp.async.wait_group 1;" ::: "memory");
        } else {
            asm volatile("cp.async.wait_group 0;" ::: "memory");
        }
        __syncthreads();
        char* buf = dsm + (sc & 1) * STAGE_BYTES;
        u32 bufA = smem_u32(buf);
        int npass = (sc < 8) ? 2 : 1;

        for (int bs = 0; bs < npass; bs++) {
            u32 bufB = bufA + 16384 + bs * 9216;

            // preload B frags: 3 ni x 2 kstep-pairs via ldmatrix.x4
            u32 bfr[3][4][2];
#pragma unroll
            for (int ni = 0; ni < 3; ni++) {
#pragma unroll
                for (int kp = 0; kp < 2; kp++) {
                    int n = wn * 24 + ni * 8 + (lane & 7);
                    int g = kp * 4 + (lane >> 3);
                    u32 addr = bufB + n * 128 + ((g ^ (n & 7)) * 16);
                    u32 r0, r1, r2, r3;
                    asm volatile("ldmatrix.sync.aligned.m8n8.x4.shared.b16 {%0,%1,%2,%3}, [%4];"
                                 : "=r"(r0), "=r"(r1), "=r"(r2), "=r"(r3) : "r"(addr));
                    bfr[ni][kp * 2 + 0][0] = r0; bfr[ni][kp * 2 + 0][1] = r1;
                    bfr[ni][kp * 2 + 1][0] = r2; bfr[ni][kp * 2 + 1][1] = r3;
                }
            }
#pragma unroll
            for (int ks = 0; ks < 4; ks++) {
                u32 afr[2][4];
#pragma unroll
                for (int mi = 0; mi < 2; mi++) {
                    int r = wm * 32 + mi * 16 + (lane & 15);
                    int g = ks * 2 + (lane >> 4);
                    u32 addr = bufA + r * 128 + ((g ^ (r & 7)) * 16);
                    asm volatile("ldmatrix.sync.aligned.m8n8.x4.shared.b16 {%0,%1,%2,%3}, [%4];"
                                 : "=r"(afr[mi][0]), "=r"(afr[mi][1]),
                                   "=r"(afr[mi][2]), "=r"(afr[mi][3]) : "r"(addr));
                }
#pragma unroll
                for (int mi = 0; mi < 2; mi++)
#pragma unroll
                    for (int ni = 0; ni < 3; ni++)
                        asm volatile(
                            "mma.sync.aligned.m16n8k16.row.col.f32.bf16.bf16.f32 "
                            "{%0,%1,%2,%3}, {%4,%5,%6,%7}, {%8,%9}, {%0,%1,%2,%3};"
                            : "+f"(acc[mi][ni][0]), "+f"(acc[mi][ni][1]),
                              "+f"(acc[mi][ni][2]), "+f"(acc[mi][ni][3])
                            : "r"(afr[mi][0]), "r"(afr[mi][1]), "r"(afr[mi][2]), "r"(afr[mi][3]),
                              "r"(bfr[ni][ks][0]), "r"(bfr[ni][ks][1]));
            }
        }
        __syncthreads();
    }

    // stage accumulators to smem for class-aligned epilogue
    float* sAcc = reinterpret_cast<float*>(dsm);
#pragma unroll
    for (int mi = 0; mi < 2; mi++)
#pragma unroll
        for (int ni = 0; ni < 3; ni++)
#pragma unroll
            for (int c = 0; c < 4; c++) {
                int rl = wm * 32 + mi * 16 + (lane >> 2) + ((c >> 1) & 1) * 8;
                int cl = wn * 24 + ni * 8 + (lane & 3) * 2 + (c & 1);
                sAcc[rl * NTILE + cl] = acc[mi][ni][c];
            }
    __syncthreads();

    for (int idx = tid; idx < MTILE * CPT; idx += 384) {
        int rl = idx >> 3, cl = idx & 7;
        int cls = nt * CPT + cl;
        if (cls >= C_CLS) continue;
        int row = row0 + rl;
        float ri = g_rinv[row];
        const float* a = sAcc + rl * NTILE + cl * 9;
        float cs[8], mx = -1e30f;
#pragma unroll
        for (int j = 0; j < 8; j++) { cs[j] = a[j] * ri; mx = fmaxf(mx, cs[j]); }
        float den = 0.f, num = 0.f;
#pragma unroll
        for (int j = 0; j < 8; j++) {
            float e = __expf((cs[j] - mx) * INV_SUB_T);
            den += e; num += e * cs[j];
        }
        out[(size_t)row * C_CLS + cls] = (num / den) * INV_PRIOR_T + a[8] * ri;
    }
}

extern "C" void kernel_launch(void* const* d_in, const int* in_sizes, int n_in,
                              void* d_out, int out_size) {
    const float* h = (const float*)d_in[0];
    const float* P = (const float*)d_in[1];
    float* out = (float*)d_out;
    (void)in_sizes; (void)n_in; (void)out_size;

    cudaFuncSetAttribute(k_mm, cudaFuncAttributeMaxDynamicSharedMemorySize, SMEM_DYN);

    k_prep<<<4196, 256>>>(h, P);
    k_centers<<<100, 256>>>();
    k_bvec<<<100, 256>>>();
    k_grams<<<1100, 256>>>();
    k_solve<<<100, 256>>>();
    k_mm<<<dim3(256, NT_TILES), 384, SMEM_DYN>>>(out);
}